// round 2
// baseline (speedup 1.0000x reference)
#include <cuda_runtime.h>
#include <cstdint>

#define BDIM   128
#define BATCH  32
#define SEQ    512
#define LAB    64
#define START_ 61
#define STOP_  62
#define CHUNK  64

__global__ __launch_bounds__(BDIM, 1)
void crf_fwd_kernel(const float* __restrict__ enc,   // [B,S,L]
                    const float* __restrict__ T,     // [L,L]
                    const int*   __restrict__ lens,  // [B]
                    const int*   __restrict__ tags,  // [B,S]
                    float*       __restrict__ out)   // [2*B]
{
    __shared__ __align__(16) float e_sh[2][CHUNK * LAB];  // enc chunk double buffer
    __shared__ __align__(16) float p_sh[2][LAB];          // alpha (linear domain, scaled)
    __shared__ float wmax[4];
    __shared__ float vred[LAB];
    __shared__ float redw[4];

    const int b   = blockIdx.x;
    const int tid = threadIdx.x;
    const int j   = tid >> 1;     // label column 0..63
    const int g   = tid & 1;      // half of the i-reduction
    const int len = lens[b];
    const float* encb = enc + (size_t)b * SEQ * LAB;

    // ---- issue prefetch of enc chunks 0 and 1 (cp.async, one group each) ----
    #pragma unroll
    for (int c = 0; c < 2; ++c) {
        const float* src = encb + c * CHUNK * LAB + tid * 4;
        uint32_t dst = (uint32_t)__cvta_generic_to_shared(&e_sh[c][tid * 4]);
        #pragma unroll
        for (int k = 0; k < 8; ++k)
            asm volatile("cp.async.cg.shared.global [%0], [%1], 16;\n"
                         :: "r"(dst + k * BDIM * 16), "l"(src + k * BDIM * 4));
        asm volatile("cp.async.commit_group;\n");
    }

    // ---- E column j, rows [g*32, g*32+32) in registers (one-time) ----
    float E[32];
    #pragma unroll
    for (int k = 0; k < 32; ++k)
        E[k] = expf(T[(g * 32 + k) * LAB + j]);   // exp(NEG) == 0 exactly

    asm volatile("cp.async.wait_group 1;\n");     // chunk 0 resident
    __syncthreads();

    // alpha0[j] = T[START,j] + enc[0,j]  ->  p0 = exp(...)
    if (g == 0)
        p_sh[0][j] = expf(T[START_ * LAB + j] + e_sh[0][j]);

    int Mi = 0;   // accumulated log2 scale (exact integer), owned by tid 0
    __syncthreads();

    // ================= main recurrence: t = 1 .. len-1 =================
    #pragma unroll 4
    for (int t = 1; t < len; ++t) {
        const int c = t >> 6;
        if ((t & (CHUNK - 1)) == 0) {             // chunk boundary
            asm volatile("cp.async.wait_group 0;\n");
            __syncthreads();
            const int nb = (c + 1) * CHUNK;
            if (nb < SEQ) {                        // prefetch next chunk
                const float* src = encb + nb * LAB + tid * 4;
                uint32_t dst = (uint32_t)__cvta_generic_to_shared(
                                   &e_sh[(c + 1) & 1][tid * 4]);
                #pragma unroll
                for (int k = 0; k < 8; ++k)
                    asm volatile("cp.async.cg.shared.global [%0], [%1], 16;\n"
                                 :: "r"(dst + k * BDIM * 16), "l"(src + k * BDIM * 4));
                asm volatile("cp.async.commit_group;\n");
            }
        }

        // consume rescale factor computed 1 step ago (every 4th step)
        float sc = 1.0f;
        if ((t & 3) == 0) {
            float m = fmaxf(fmaxf(wmax[0], wmax[1]), fmaxf(wmax[2], wmax[3]));
            int e = (__float_as_int(m) >> 23) - 127;
            sc = __int_as_float((127 - e) << 23);   // exact 2^-e
            if (tid == 0) Mi += e;
        }

        // u = exp(enc[t,j]) — independent of p, overlaps the matvec
        float u = __expf(e_sh[c & 1][(t & (CHUNK - 1)) * LAB + j]);

        // q_j(partial) = sum_{i in my half} p[i] * E[i][j]
        const float4* pv = reinterpret_cast<const float4*>(&p_sh[(t - 1) & 1][g * 32]);
        float q0 = 0.f, q1 = 0.f, q2 = 0.f, q3 = 0.f;
        #pragma unroll
        for (int k = 0; k < 8; ++k) {
            float4 v = pv[k];
            q0 = fmaf(v.x, E[4 * k + 0], q0);
            q1 = fmaf(v.y, E[4 * k + 1], q1);
            q2 = fmaf(v.z, E[4 * k + 2], q2);
            q3 = fmaf(v.w, E[4 * k + 3], q3);
        }
        float q = (q0 + q1) + (q2 + q3);
        q += __shfl_xor_sync(0xffffffffu, q, 1);    // merge the two halves

        float p = q * u * sc;
        if (g == 0) p_sh[t & 1][j] = p;

        if ((t & 3) == 3) {                         // produce next rescale factor
            // warp max: j duplicated across xor-1 lane pairs -> 4 levels suffice
            float wm = p;
            wm = fmaxf(wm, __shfl_xor_sync(0xffffffffu, wm, 2));
            wm = fmaxf(wm, __shfl_xor_sync(0xffffffffu, wm, 4));
            wm = fmaxf(wm, __shfl_xor_sync(0xffffffffu, wm, 8));
            wm = fmaxf(wm, __shfl_xor_sync(0xffffffffu, wm, 16));
            if ((tid & 31) == 0) wmax[tid >> 5] = wm;
        }
        __syncthreads();
    }

    // ================= epilogue =================
    const int lastbuf = (len - 1) & 1;
    if (g == 0)
        vred[j] = p_sh[lastbuf][j] * expf(T[j * LAB + STOP_]);

    // labeled score: strided gather-sum over t
    float lsum = 0.0f;
    const int* tagb = tags + b * SEQ;
    for (int t = 1 + tid; t < len; t += BDIM) {
        int tg = tagb[t], tp = tagb[t - 1];
        lsum += T[tp * LAB + tg] + encb[t * LAB + tg];
    }
    #pragma unroll
    for (int m = 16; m; m >>= 1)
        lsum += __shfl_xor_sync(0xffffffffu, lsum, m);
    if ((tid & 31) == 0) redw[tid >> 5] = lsum;
    __syncthreads();

    if (tid == 0) {
        float ssum = 0.0f;
        #pragma unroll
        for (int k = 0; k < LAB; ++k) ssum += vred[k];
        out[b] = (float)((double)Mi * 0.6931471805599453 + (double)logf(ssum));

        int t0g = tagb[0];
        int eg  = tagb[len - 1];
        out[BATCH + b] = redw[0] + redw[1] + redw[2] + redw[3]
                       + T[START_ * LAB + t0g] + encb[t0g]
                       + T[eg * LAB + STOP_];
    }
}

extern "C" void kernel_launch(void* const* d_in, const int* in_sizes, int n_in,
                              void* d_out, int out_size)
{
    const float* enc  = (const float*)d_in[0];   // encoder_scores [32,512,64]
    const float* T    = (const float*)d_in[1];   // transition [64,64]
    const int*   lens = (const int*)  d_in[2];   // word_seq_lens [32]
    const int*   tags = (const int*)  d_in[3];   // tags [32,512]
    // d_in[4] = mask — recomputed from lens, unused
    float* out = (float*)d_out;                  // [64]: unlabeled(32) ++ labeled(32)

    crf_fwd_kernel<<<BATCH, BDIM>>>(enc, T, lens, tags, out);
}

// round 3
// speedup vs baseline: 1.4029x; 1.4029x over previous
#include <cuda_runtime.h>
#include <cstdint>

#define BDIM   128
#define BATCH  32
#define SEQ    512
#define LAB    64
#define START_ 61
#define STOP_  62
#define CHUNK  64

#define FMA2(d,a,b,c)  asm("fma.rn.f32x2 %0, %1, %2, %3;" : "=l"(d) : "l"(a), "l"(b), "l"(c))
#define ADD2(d,a,b)    asm("add.rn.f32x2 %0, %1, %2;"     : "=l"(d) : "l"(a), "l"(b))
#define PACK2(d,lo,hi) asm("mov.b64 %0, {%1, %2};"        : "=l"(d) : "f"(lo), "f"(hi))
#define UNPACK2(lo,hi,s) asm("mov.b64 {%0, %1}, %2;"      : "=f"(lo), "=f"(hi) : "l"(s))

__global__ __launch_bounds__(BDIM, 1)
void crf_fwd_kernel(const float* __restrict__ enc,   // [B,S,L]
                    const float* __restrict__ T,     // [L,L]
                    const int*   __restrict__ lens,  // [B]
                    const int*   __restrict__ tags,  // [B,S]
                    float*       __restrict__ out)   // [2*B]
{
    __shared__ __align__(16) float e_sh[2][CHUNK * LAB];  // enc chunk double buffer
    __shared__ __align__(16) float p_sh[2][72];           // p[0..31] at [0..31], p[32..63] at [36..67]
    __shared__ float vred[LAB];
    __shared__ float redw[4];

    const int b   = blockIdx.x;
    const int tid = threadIdx.x;
    const int j   = tid >> 1;      // label column 0..63
    const int g   = tid & 1;       // which 32-row half of the i-reduction
    const int len = lens[b];
    const float* encb = enc + (size_t)b * SEQ * LAB;
    const int idx = (j < 32) ? j : j + 4;   // padded store slot for column j

    // ---- prefetch enc chunks 0 and 1 (one cp.async group each) ----
    #pragma unroll
    for (int c = 0; c < 2; ++c) {
        const float* src = encb + c * CHUNK * LAB + tid * 4;
        uint32_t dst = (uint32_t)__cvta_generic_to_shared(&e_sh[c][tid * 4]);
        #pragma unroll
        for (int k = 0; k < 8; ++k)
            asm volatile("cp.async.cg.shared.global [%0], [%1], 16;\n"
                         :: "r"(dst + k * BDIM * 16), "l"(src + k * BDIM * 4));
        asm volatile("cp.async.commit_group;\n");
    }

    // ---- E column j, rows [g*32, g*32+32), packed as 16 f32x2 pairs ----
    unsigned long long E2[16];
    #pragma unroll
    for (int k = 0; k < 16; ++k) {
        float lo = expf(T[(g * 32 + 2 * k)     * LAB + j]);  // exp(NEG) == 0 exactly
        float hi = expf(T[(g * 32 + 2 * k + 1) * LAB + j]);
        PACK2(E2[k], lo, hi);
    }

    asm volatile("cp.async.wait_group 1;\n");    // chunk 0 resident
    __syncthreads();

    if (g == 0)
        p_sh[0][idx] = expf(T[START_ * LAB + j] + e_sh[0][j]);

    int Mi = 0;                                  // accumulated log2 scale (same in every thread)
    __syncthreads();

    const int nch = ((len - 1) >> 6) + 1;        // chunks containing steps 1..len-1
    int t = 1;

    for (int c = 0; c < nch; ++c) {
        if (c >= 1) {
            const int nc = c + 1;
            if (nc < nch) {                      // prefetch chunk c+1
                const float* src = encb + nc * CHUNK * LAB + tid * 4;
                uint32_t dst = (uint32_t)__cvta_generic_to_shared(
                                   &e_sh[nc & 1][tid * 4]);
                #pragma unroll
                for (int k = 0; k < 8; ++k)
                    asm volatile("cp.async.cg.shared.global [%0], [%1], 16;\n"
                                 :: "r"(dst + k * BDIM * 16), "l"(src + k * BDIM * 4));
                asm volatile("cp.async.commit_group;\n");
                asm volatile("cp.async.wait_group 1;\n");   // chunk c resident
            } else {
                asm volatile("cp.async.wait_group 0;\n");
            }
            __syncthreads();
        }

        const float* eb = e_sh[c & 1];
        const int tt0   = t - c * CHUNK;                 // 1 for c==0, else 0
        const int ttend = min(CHUNK, len - c * CHUNK);   // steps with t < len

        #pragma unroll 4
        for (int tt = tt0; tt < ttend; ++tt, ++t) {
            const float* pp = &p_sh[(t - 1) & 1][0];

            // u = exp(enc[t,j]); per-step exact 2^-e0 rescale from p[0]'s exponent
            float u  = __expf(eb[tt * LAB + j]);
            float p0 = pp[0];                            // broadcast LDS
            int   e0 = ((__float_as_int(p0) >> 23) & 255) - 127;
            float sc = __int_as_float((127 - e0) << 23); // exact 2^-e0
            Mi += e0;
            float us = u * sc;                           // off the q critical path

            // q_j(partial) = sum over my 32-row half, packed f32x2 FMAs
            const ulonglong2* pv =
                reinterpret_cast<const ulonglong2*>(pp + g * 36);
            unsigned long long a0 = 0, a1 = 0, a2 = 0, a3 = 0;
            #pragma unroll
            for (int k = 0; k < 4; ++k) {
                ulonglong2 v  = pv[2 * k];
                ulonglong2 w  = pv[2 * k + 1];
                FMA2(a0, v.x, E2[4 * k + 0], a0);
                FMA2(a1, v.y, E2[4 * k + 1], a1);
                FMA2(a2, w.x, E2[4 * k + 2], a2);
                FMA2(a3, w.y, E2[4 * k + 3], a3);
            }
            unsigned long long s01, s23, s;
            ADD2(s01, a0, a1);
            ADD2(s23, a2, a3);
            ADD2(s, s01, s23);
            float lo, hi;
            UNPACK2(lo, hi, s);
            float q = lo + hi;
            q += __shfl_xor_sync(0xffffffffu, q, 1);     // merge the two halves

            float p = q * us;
            if (g == 0) p_sh[t & 1][idx] = p;
            __syncthreads();
        }
    }

    // ================= epilogue =================
    const int lastbuf = (len - 1) & 1;
    if (g == 0)
        vred[j] = p_sh[lastbuf][idx] * expf(T[j * LAB + STOP_]);

    // labeled score: strided gather-sum over t
    float lsum = 0.0f;
    const int* tagb = tags + b * SEQ;
    for (int t2 = 1 + tid; t2 < len; t2 += BDIM) {
        int tg = tagb[t2], tp = tagb[t2 - 1];
        lsum += T[tp * LAB + tg] + encb[t2 * LAB + tg];
    }
    #pragma unroll
    for (int m = 16; m; m >>= 1)
        lsum += __shfl_xor_sync(0xffffffffu, lsum, m);
    if ((tid & 31) == 0) redw[tid >> 5] = lsum;
    __syncthreads();

    if (tid == 0) {
        float ssum = 0.0f;
        #pragma unroll
        for (int k = 0; k < LAB; ++k) ssum += vred[k];
        out[b] = (float)((double)Mi * 0.6931471805599453 + (double)logf(ssum));

        int t0g = tagb[0];
        int eg  = tagb[len - 1];
        out[BATCH + b] = redw[0] + redw[1] + redw[2] + redw[3]
                       + T[START_ * LAB + t0g] + encb[t0g]
                       + T[eg * LAB + STOP_];
    }
}

extern "C" void kernel_launch(void* const* d_in, const int* in_sizes, int n_in,
                              void* d_out, int out_size)
{
    const float* enc  = (const float*)d_in[0];   // encoder_scores [32,512,64]
    const float* T    = (const float*)d_in[1];   // transition [64,64]
    const int*   lens = (const int*)  d_in[2];   // word_seq_lens [32]
    const int*   tags = (const int*)  d_in[3];   // tags [32,512]
    // d_in[4] = mask — recomputed from lens, unused
    float* out = (float*)d_out;                  // [64]: unlabeled(32) ++ labeled(32)

    crf_fwd_kernel<<<BATCH, BDIM>>>(enc, T, lens, tags, out);
}